// round 6
// baseline (speedup 1.0000x reference)
#include <cuda_runtime.h>

// PLIF spiking neuron forward:
//   x: [B=32, T=8, C=128, H=32, W=32] f32, tau: [C=128] f32
//   tau_s = sigmoid(tau[c]); scan over t:
//     mem = mem*tau_s + x_t; spike = (mem > 1); mem = (1-spike)*mem
//
// Persistent single-wave layout exploiting problem structure:
//   1024 CTAs x 256 threads, each thread does EXACTLY 4 sites.
//   Per-thread site stride = 2^20 elements = TCHW, so between iterations
//   only b changes (b += 8); rem, c, and sigmoid(tau[c]) are loop-invariant
//   and fully hoisted. Loop body = base += const; 8x LDG.128; scan; 8x STG.128.
//   All 1024 CTAs co-resident (capacity 1184 @ 32 regs) -> no tail wave.

constexpr int B = 32, T = 8, C = 128, H = 32, W = 32;
constexpr int HW   = H * W;          // 1024
constexpr int CHW  = C * HW;         // 131072 (= 2^17)
constexpr int TCHW = T * CHW;        // 1048576 (= 2^20)
constexpr int N4   = (B * CHW) / 4;  // 1048576 float4-sites

constexpr int THREADS = 256;
constexpr int BLOCKS  = 1024;        // 1024*256*4 = N4 exactly
constexpr int ITERS   = 4;

__global__ __launch_bounds__(THREADS) void plif_kernel(
    const float4* __restrict__ x4,
    const float*  __restrict__ tau,
    float4*       __restrict__ out4)
{
    constexpr int tstride = CHW >> 2;            // float4 stride between timesteps
    // per-iteration advance: b += 8  =>  +8*TCHW elements = +2*TCHW float4s
    constexpr int iter_stride = 2 * TCHW;        // in float4 units

    int idx = blockIdx.x * THREADS + threadIdx.x;    // [0, 2^18)
    int e   = idx << 2;                               // [0, 2^20)
    int b0  = e >> 17;                                // [0, 8)
    int rem = e & (CHW - 1);
    int c   = rem >> 10;

    // loop-invariant per-channel leak (precise sigmoid)
    float ts = 1.0f / (1.0f + expf(-tau[c]));

    int base = (b0 * TCHW + rem) >> 2;               // float4 index of t=0

#pragma unroll 1
    for (int it = 0; it < ITERS; it++, base += iter_stride) {
        // Front-batched loads: 8 independent LDG.128 in flight
        float4 v[T];
#pragma unroll
        for (int t = 0; t < T; t++)
            v[t] = x4[base + t * tstride];

        // Register scan; store each spike immediately so v[t] is freed
        float4 mem = make_float4(0.f, 0.f, 0.f, 0.f);
#pragma unroll
        for (int t = 0; t < T; t++) {
            float4 s;
            mem.x = mem.x * ts + v[t].x;
            mem.y = mem.y * ts + v[t].y;
            mem.z = mem.z * ts + v[t].z;
            mem.w = mem.w * ts + v[t].w;
            s.x = (mem.x > 1.0f) ? 1.0f : 0.0f;
            s.y = (mem.y > 1.0f) ? 1.0f : 0.0f;
            s.z = (mem.z > 1.0f) ? 1.0f : 0.0f;
            s.w = (mem.w > 1.0f) ? 1.0f : 0.0f;
            // hard reset: mem = (1-spike)*mem
            if (s.x != 0.0f) mem.x = 0.0f;
            if (s.y != 0.0f) mem.y = 0.0f;
            if (s.z != 0.0f) mem.z = 0.0f;
            if (s.w != 0.0f) mem.w = 0.0f;
            out4[base + t * tstride] = s;
        }
    }
}

extern "C" void kernel_launch(void* const* d_in, const int* in_sizes, int n_in,
                              void* d_out, int out_size)
{
    const float4* x4  = (const float4*)d_in[0];
    const float*  tau = (const float*)d_in[1];
    float4*       o4  = (float4*)d_out;

    plif_kernel<<<BLOCKS, THREADS>>>(x4, tau, o4);
}

// round 7
// speedup vs baseline: 1.1432x; 1.1432x over previous
#include <cuda_runtime.h>

// PLIF spiking neuron forward:
//   x: [B=32, T=8, C=128, H=32, W=32] f32, tau: [C=128] f32
//   tau_s = sigmoid(tau[c])
//   scan over t: mem = mem*tau_s + x_t; spike = (mem - 1 > 0); mem = (1-spike)*mem
//   out: spikes, same shape as x.
//
// FINAL (R2 structure — proven fastest across 5 variants):
//   Pure 256 MiB streaming workload at the mixed-R/W HBM plateau (~5.8 TB/s,
//   73% of spec). One thread owns one (b,c,w-quad) site via float4:
//   8 front-batched LDG.128 (MLP=8), register scan, interleaved STG.128
//   (store inside the loop so each v[t] dies immediately -> 32 regs,
//   8 CTAs/SM, ~81% occupancy). Cache-streaming hints, store batching,
//   grid-stride, and persistent layouts all measured slower (R3-R6).

constexpr int B = 32, T = 8, C = 128, H = 32, W = 32;
constexpr int HW   = H * W;          // 1024
constexpr int CHW  = C * HW;         // 131072 (= 2^17)
constexpr int TCHW = T * CHW;        // 1048576
constexpr int N4   = (B * CHW) / 4;  // 1048576 float4-threads

__global__ __launch_bounds__(256) void plif_kernel(
    const float4* __restrict__ x4,
    const float*  __restrict__ tau,
    float4*       __restrict__ out4)
{
    int idx = blockIdx.x * blockDim.x + threadIdx.x;
    if (idx >= N4) return;

    int e   = idx << 2;              // element index within [B, C, H, W] flat
    int b   = e >> 17;               // / CHW
    int rem = e & (CHW - 1);         // within one (C,H,W) slab
    int c   = rem >> 10;             // / HW

    // per-channel leak (broadcast within warp; precise sigmoid)
    float ts = 1.0f / (1.0f + expf(-tau[c]));

    // float4 base index of timestep 0 for this site
    int base = (b * TCHW + rem) >> 2;
    constexpr int tstride = CHW >> 2;  // float4 stride between timesteps

    // Front-batched loads: 8 independent LDG.128 in flight
    float4 v[T];
#pragma unroll
    for (int t = 0; t < T; t++)
        v[t] = x4[base + t * tstride];

    // Register scan; store each spike immediately so v[t] is freed
    float4 mem = make_float4(0.f, 0.f, 0.f, 0.f);
#pragma unroll
    for (int t = 0; t < T; t++) {
        float4 s;
        mem.x = mem.x * ts + v[t].x;
        mem.y = mem.y * ts + v[t].y;
        mem.z = mem.z * ts + v[t].z;
        mem.w = mem.w * ts + v[t].w;
        s.x = (mem.x > 1.0f) ? 1.0f : 0.0f;
        s.y = (mem.y > 1.0f) ? 1.0f : 0.0f;
        s.z = (mem.z > 1.0f) ? 1.0f : 0.0f;
        s.w = (mem.w > 1.0f) ? 1.0f : 0.0f;
        // hard reset: mem = (1-spike)*mem
        if (s.x != 0.0f) mem.x = 0.0f;
        if (s.y != 0.0f) mem.y = 0.0f;
        if (s.z != 0.0f) mem.z = 0.0f;
        if (s.w != 0.0f) mem.w = 0.0f;
        out4[base + t * tstride] = s;
    }
}

extern "C" void kernel_launch(void* const* d_in, const int* in_sizes, int n_in,
                              void* d_out, int out_size)
{
    const float4* x4  = (const float4*)d_in[0];
    const float*  tau = (const float*)d_in[1];
    float4*       o4  = (float4*)d_out;

    int threads = 256;
    int blocks  = (N4 + threads - 1) / threads;  // 4096
    plif_kernel<<<blocks, threads>>>(x4, tau, o4);
}